// round 13
// baseline (speedup 1.0000x reference)
#include <cuda_runtime.h>

#define BB 64
#define TT 512
#define II 512
#define HH 1024

#define NBLK 128
#define NTHR 512

// [g][t][b][h] input-side gate pre-activations (402 MB)
__device__ float g_xg[(size_t)3 * TT * BB * HH];
// double-buffered hidden state
__device__ float g_h[2][BB * HH];
// grid barrier state
__device__ unsigned g_bar;
__device__ unsigned g_gen;

__device__ __forceinline__ void gridbar(unsigned& gen) {
    __syncthreads();
    gen++;
    if (threadIdx.x == 0) {
        __threadfence();
        unsigned arr = atomicAdd(&g_bar, 1u);
        if (arr == NBLK - 1) {
            g_bar = 0;
            __threadfence();
            atomicExch(&g_gen, gen);
        } else {
            volatile unsigned* vg = &g_gen;
            while (*vg < gen) { }
            __threadfence();
        }
    }
    __syncthreads();
}

__device__ __forceinline__ void cp_async16(void* smem_dst, const void* gsrc) {
    unsigned s = (unsigned)__cvta_generic_to_shared(smem_dst);
    asm volatile("cp.async.cg.shared.global [%0], [%1], 16;\n" :: "r"(s), "l"(gsrc));
}
#define CP_COMMIT() asm volatile("cp.async.commit_group;\n" ::: "memory")
#define CP_WAIT(n)  asm volatile("cp.async.wait_group %0;\n" :: "n"(n) : "memory")

#define FMA2(d, a, b) asm("fma.rn.f32x2 %0, %1, %2, %0;" : "+l"(d) : "l"(a), "l"(b))
#define DUP2(d, s)    asm("mov.b64 %0, {%1, %1};" : "=l"(d) : "r"(__float_as_uint(s)))

// ---------------------------------------------------------------------------
// Phase 1 v4: same math/layout as v3 (proven numerics) but PIPELINED:
// double-buffered As/Bs, weights+x for k-block kb+1 held in registers across
// the single per-iter __syncthreads, LDG for kb+2 issued 2 iters ahead.
// One sync per k-block (was 2) and LDG latency fully hidden.
// ---------------------------------------------------------------------------
__global__ __launch_bounds__(256, 2) void gemm_in(
    const float* __restrict__ x,
    const float* __restrict__ W0, const float* __restrict__ W1, const float* __restrict__ W2,
    const float* __restrict__ c0, const float* __restrict__ c1, const float* __restrict__ c2)
{
    __shared__ float As[2][16][128];   // 16 KB
    __shared__ float Bs[2][16][64];    //  8 KB
    const int g = blockIdx.z;
    const float* W    = (g == 0) ? W0 : (g == 1) ? W1 : W2;
    const float* bias = (g == 0) ? c0 : (g == 1) ? c1 : c2;
    const int m0 = blockIdx.y * 128;
    const int n0 = blockIdx.x * 64;
    const int tid = threadIdx.x;
    const int n_thr = tid & 15;
    const int m_thr = tid >> 4;
    const int ar = tid >> 1, ak = (tid & 1) * 8;
    const int brow = tid >> 2, bk = (tid & 3) * 4;

    const float* xa = &x[(size_t)(m0 + ar) * II + ak];
    const float* wb = &W[(size_t)(n0 + brow) * II + bk];

    unsigned long long acc2[8][2];
#pragma unroll
    for (int i = 0; i < 8; i++) { acc2[i][0] = 0ull; acc2[i][1] = 0ull; }

    float4 a0[2], a1[2], bv[2];
    // prologue: k-block 0 into regs -> smem buf0; k-block 1 into regs.
    a0[0] = *(const float4*)(xa + 0);
    a1[0] = *(const float4*)(xa + 4);
    bv[0] = *(const float4*)(wb + 0);
    {
        As[0][ak + 0][ar] = a0[0].x; As[0][ak + 1][ar] = a0[0].y;
        As[0][ak + 2][ar] = a0[0].z; As[0][ak + 3][ar] = a0[0].w;
        As[0][ak + 4][ar] = a1[0].x; As[0][ak + 5][ar] = a1[0].y;
        As[0][ak + 6][ar] = a1[0].z; As[0][ak + 7][ar] = a1[0].w;
        Bs[0][bk + 0][brow] = bv[0].x; Bs[0][bk + 1][brow] = bv[0].y;
        Bs[0][bk + 2][brow] = bv[0].z; Bs[0][bk + 3][brow] = bv[0].w;
    }
    a0[1] = *(const float4*)(xa + 16);
    a1[1] = *(const float4*)(xa + 20);
    bv[1] = *(const float4*)(wb + 16);
    __syncthreads();

    int cur = 0;
    for (int kb = 0; kb < 32; kb++) {
        const int nxt = kb + 1;
        // stage k-block kb+1 into the idle buffer (its last reader finished
        // at the sync closing iter kb-1), and prefetch kb+2 into the freed regs
        if (nxt < 32) {
            const int s = nxt & 1;
            As[cur ^ 1][ak + 0][ar] = a0[s].x; As[cur ^ 1][ak + 1][ar] = a0[s].y;
            As[cur ^ 1][ak + 2][ar] = a0[s].z; As[cur ^ 1][ak + 3][ar] = a0[s].w;
            As[cur ^ 1][ak + 4][ar] = a1[s].x; As[cur ^ 1][ak + 5][ar] = a1[s].y;
            As[cur ^ 1][ak + 6][ar] = a1[s].z; As[cur ^ 1][ak + 7][ar] = a1[s].w;
            Bs[cur ^ 1][bk + 0][brow] = bv[s].x; Bs[cur ^ 1][bk + 1][brow] = bv[s].y;
            Bs[cur ^ 1][bk + 2][brow] = bv[s].z; Bs[cur ^ 1][bk + 3][brow] = bv[s].w;
        }
        if (kb + 2 < 32) {
            const int s = kb & 1;
            a0[s] = *(const float4*)(xa + (kb + 2) * 16);
            a1[s] = *(const float4*)(xa + (kb + 2) * 16 + 4);
            bv[s] = *(const float4*)(wb + (kb + 2) * 16);
        }
#pragma unroll
        for (int k = 0; k < 16; k++) {
            float a[8];
            *(float4*)&a[0] = *(const float4*)&As[cur][k][m_thr * 8];
            *(float4*)&a[4] = *(const float4*)&As[cur][k][m_thr * 8 + 4];
            union { float4 f; unsigned long long u[2]; } bb;
            bb.f = *(const float4*)&Bs[cur][k][n_thr * 4];
#pragma unroll
            for (int i = 0; i < 8; i++) {
                unsigned long long a2;
                DUP2(a2, a[i]);
                FMA2(acc2[i][0], a2, bb.u[0]);
                FMA2(acc2[i][1], a2, bb.u[1]);
            }
        }
        __syncthreads();
        cur ^= 1;
    }

    float4 bs4 = *(const float4*)&bias[n0 + n_thr * 4];
#pragma unroll
    for (int i = 0; i < 8; i++) {
        int m = m0 + m_thr * 8 + i;
        int b = m >> 9;      // m = b*T + t, T = 512
        int t = m & 511;
        union { unsigned long long u; float f[2]; } lo, hi;
        lo.u = acc2[i][0]; hi.u = acc2[i][1];
        float4 o;
        o.x = lo.f[0] + bs4.x; o.y = lo.f[1] + bs4.y;
        o.z = hi.f[0] + bs4.z; o.w = hi.f[1] + bs4.w;
        *(float4*)&g_xg[(((size_t)g * TT + t) * BB + b) * HH + n0 + n_thr * 4] = o;
    }
}

// ---------------------------------------------------------------------------
// Phase 2 v4: persistent kernel, 128 blocks x 512 threads (16 warps, 4/SMSP).
// Warp w owns k-slice [w*64, w*64+64) for all 8 h-cols and all 64 batches.
// Lane = hp*4 + ksub: h-col h0+hp; k = w*64 + ksub*4 + j*16 + {0..3}, j=0..3.
// Weights/thread: 1h x 3g x 16k = 48 floats = 24 packed b64 pairs (48 regs).
// Per (thread,batch): 4 LDS.128 + 24 FFMA2 + 6 SHFL -> issue 9.7K < FMA 12.3K
// cyc/step/SMSP: FMA-pipe bound with 4 warps/SMSP hiding SHFL/LDS latency.
// red[16][64][8][3] in smem; epilogue: 1 output/thread, 16-way smem reduce.
// ---------------------------------------------------------------------------
__global__ __launch_bounds__(NTHR, 1) void gru_steps(
    const float* __restrict__ Whr, const float* __restrict__ Whi, const float* __restrict__ Whn,
    float* __restrict__ out, int write_hlast)
{
    extern __shared__ float smem[];
    float* hbuf = smem;                    // [2][8][1024] = 16384 floats (64 KB)
    float* red  = smem + 2 * 8 * HH;       // [16w][64b][8h][3g] = 24576 floats (96 KB)

    const int tid  = threadIdx.x;
    const int warp = tid >> 5;             // 0..15 : k-slice
    const int lane = tid & 31;
    const int hp   = lane >> 2;            // 0..7 : h column
    const int ksub = lane & 3;             // 0..3
    const int ht = blockIdx.x;
    const int h0 = ht * 8;
    const int kbase = warp * 64 + ksub * 4;

    // ---- Weights to registers (persist across all 512 steps). ----
    // Pair j*2+p covers k = kbase + j*16 + p*2 .. +1.
    unsigned long long wr[8], wi[8], wn[8];
    {
        const size_t row = (size_t)(h0 + hp) * HH + kbase;
#pragma unroll
        for (int j = 0; j < 4; j++) {
#pragma unroll
            for (int p = 0; p < 2; p++) {
                const size_t o = j * 16 + p * 2;
                wr[j * 2 + p] = *(const unsigned long long*)&Whr[row + o];
                wi[j * 2 + p] = *(const unsigned long long*)&Whi[row + o];
                wn[j * 2 + p] = *(const unsigned long long*)&Whn[row + o];
            }
        }
    }

    // Zero h[0] (this block's 512-float slice).
    g_h[0][ht * 512 + tid] = 0.f;

    unsigned gen = *(volatile unsigned*)&g_gen;
    gridbar(gen);

    // Epilogue: one output per thread.
    const int b_o = tid >> 3, hh_o = tid & 7;
    const size_t ixo = (size_t)b_o * HH + h0 + hh_o;

    for (int t = 0; t < TT; t++) {
        const float* hcur = g_h[t & 1];
        float* hnxt = g_h[(t & 1) ^ 1];

        // ---- Prefetch epilogue operands (independent of recurrence). ----
        const size_t xoff = (size_t)t * BB * HH;
        float xr0 = g_xg[xoff + ixo];
        float xi0 = g_xg[(size_t)TT * BB * HH + xoff + ixo];
        float xn0 = g_xg[2 * (size_t)TT * BB * HH + xoff + ixo];
        float hp0 = __ldcg(&hcur[ixo]);

        // Stage chunk 0 (batches 0..7): 32 KB, L1-bypassed.
        {
#pragma unroll
            for (int i = 0; i < 4; i++) {
                int idx = (tid + i * NTHR) * 4;
                cp_async16(hbuf + idx, hcur + idx);
            }
            CP_COMMIT();
        }

        for (int c = 0; c < 8; c++) {
            if (c < 7) {
                __syncthreads();             // WAR: target buf fully consumed
                const float* src = hcur + (c + 1) * 8 * HH;
                float* dst = hbuf + ((c + 1) & 1) * (8 * HH);
#pragma unroll
                for (int i = 0; i < 4; i++) {
                    int idx = (tid + i * NTHR) * 4;
                    cp_async16(dst + idx, src + idx);
                }
                CP_COMMIT();
                CP_WAIT(1);                  // chunk c arrived
            } else {
                CP_WAIT(0);
            }
            __syncthreads();                 // chunk c visible to all warps

            const float* hc = hbuf + (c & 1) * (8 * HH) + kbase;
#pragma unroll
            for (int bb = 0; bb < 8; bb++) {
                const int b = c * 8 + bb;
                unsigned long long ar2 = 0, ai2 = 0, an2 = 0;
                const float* hrow = hc + bb * HH;
#pragma unroll
                for (int j = 0; j < 4; j++) {
                    union { float4 f; unsigned long long u[2]; } hv;
                    hv.f = *(const float4*)(hrow + j * 16);
                    FMA2(ar2, wr[j * 2 + 0], hv.u[0]);
                    FMA2(ai2, wi[j * 2 + 0], hv.u[0]);
                    FMA2(an2, wn[j * 2 + 0], hv.u[0]);
                    FMA2(ar2, wr[j * 2 + 1], hv.u[1]);
                    FMA2(ai2, wi[j * 2 + 1], hv.u[1]);
                    FMA2(an2, wn[j * 2 + 1], hv.u[1]);
                }
                union { unsigned long long u; float f[2]; } ur, ui, un;
                ur.u = ar2; ui.u = ai2; un.u = an2;
                float sr = ur.f[0] + ur.f[1];
                float si = ui.f[0] + ui.f[1];
                float sn = un.f[0] + un.f[1];
                // reduce over 4 ksub lanes
                sr += __shfl_xor_sync(0xFFFFFFFFu, sr, 1);
                si += __shfl_xor_sync(0xFFFFFFFFu, si, 1);
                sn += __shfl_xor_sync(0xFFFFFFFFu, sn, 1);
                sr += __shfl_xor_sync(0xFFFFFFFFu, sr, 2);
                si += __shfl_xor_sync(0xFFFFFFFFu, si, 2);
                sn += __shfl_xor_sync(0xFFFFFFFFu, sn, 2);
                if (ksub == 0) {
                    float* rp = &red[(((warp * 64) + b) * 8 + hp) * 3];
                    rp[0] = sr; rp[1] = si; rp[2] = sn;
                }
            }
        }

        __syncthreads();   // red[] complete

        // ---- Reduce over 16 warp k-slices + gate epilogue (1 out/thread). ----
        {
            float sr = 0.f, si = 0.f, sn = 0.f;
#pragma unroll
            for (int w = 0; w < 16; w++) {
                const float* rp = &red[(((w * 64) + b_o) * 8 + hh_o) * 3];
                sr += rp[0]; si += rp[1]; sn += rp[2];
            }
            float rg = __fdividef(1.f, 1.f + __expf(-(xr0 + sr)));
            float ig = __fdividef(1.f, 1.f + __expf(-(xi0 + si)));
            float zi = xn0 + rg * sn;
            float ng = 1.f - __fdividef(2.f, __expf(2.f * zi) + 1.f);   // tanh(zi)
            float hn = (1.f - ig) * ng + ig * hp0;
            hnxt[ixo] = hn;
            out[((size_t)b_o * TT + t) * HH + h0 + hh_o] = hn;
            if (write_hlast && t == TT - 1)
                out[(size_t)BB * TT * HH + ixo] = hn;
        }

        if (t < TT - 1) gridbar(gen);
    }
}

extern "C" void kernel_launch(void* const* d_in, const int* in_sizes, int n_in,
                              void* d_out, int out_size) {
    const float* x   = (const float*)d_in[0];
    const float* Wir = (const float*)d_in[1];
    const float* Wii = (const float*)d_in[2];
    const float* Win = (const float*)d_in[3];
    const float* bir = (const float*)d_in[4];
    const float* bii = (const float*)d_in[5];
    const float* bin = (const float*)d_in[6];
    const float* Whr = (const float*)d_in[7];
    const float* Whi = (const float*)d_in[8];
    const float* Whn = (const float*)d_in[9];
    float* out = (float*)d_out;

    // Phase 1: input-side projections for all 3 gates (pipelined).
    dim3 g1(HH / 64, (BB * TT) / 128, 3);
    gemm_in<<<g1, 256>>>(x, Wir, Wii, Win, bir, bii, bin);

    // Phase 2: persistent recurrence kernel (16 warps/block).
    const int smem_bytes = (2 * 8 * HH + 16 * 64 * 8 * 3) * (int)sizeof(float);  // 163840
    cudaFuncSetAttribute(gru_steps, cudaFuncAttributeMaxDynamicSharedMemorySize, smem_bytes);
    int write_hlast = (out_size >= BB * TT * HH + BB * HH) ? 1 : 0;
    gru_steps<<<NBLK, NTHR, smem_bytes>>>(Whr, Whi, Whn, out, write_hlast);
}